// round 16
// baseline (speedup 1.0000x reference)
#include <cuda_runtime.h>
#include <cuda_fp16.h>
#include <cstdint>

// ============================================================================
// LSTMCell on GB300 via mma.sync (HMMA) — tcgen05 unavailable (compute_103 PTX).
// gates[B,512] = [x|h] @ Wcat^T, fp16 operands / fp32 accum, fused epilogue.
//
// R15 -> R16: TRUE single-kernel fusion with NO gmem A buffer. Each CTA
// converts its own 256-row A tile (fp32 gmem -> fp16 fragment layout) into
// 128KB of smem (fits beside 64KB W: 197KB total), syncs, then runs the R12
// GEMM with A via conflict-free LDS.128. Producer==consumer -> no coherence
// hazards, no prepass launch, no 64MB of g_a DRAM traffic.
// ============================================================================

__device__ __forceinline__ uint32_t smem_u32(const void* p) {
    uint32_t a;
    asm("{ .reg .u64 t; cvta.to.shared.u64 t, %1; cvt.u32.u64 %0, t; }"
        : "=r"(a) : "l"(p));
    return a;
}

__device__ __forceinline__ float fast_tanh(float x) {
    float r;
    asm("tanh.approx.f32 %0, %1;" : "=f"(r) : "f"(x));
    return r;
}
__device__ __forceinline__ float fast_sigmoid(float x) {
    return fmaf(0.5f, fast_tanh(0.5f * x), 0.5f);
}

__device__ __forceinline__ uint32_t cvt_h2(float lo, float hi) {
    uint32_t r;
    asm("cvt.rn.f16x2.f32 %0, %1, %2;" : "=r"(r) : "f"(hi), "f"(lo));
    return r;
}

__device__ __forceinline__ void mma16816(float* d, const uint32_t* a,
                                         uint32_t b0, uint32_t b1) {
    asm volatile(
        "mma.sync.aligned.m16n8k16.row.col.f32.f16.f16.f32 "
        "{%0,%1,%2,%3}, {%4,%5,%6,%7}, {%8,%9}, {%0,%1,%2,%3};\n"
        : "+f"(d[0]), "+f"(d[1]), "+f"(d[2]), "+f"(d[3])
        : "r"(a[0]), "r"(a[1]), "r"(a[2]), "r"(a[3]), "r"(b0), "r"(b1));
}

__device__ __forceinline__ void lds128(uint32_t* r, uint32_t addr) {
    asm volatile("ld.shared.v4.b32 {%0,%1,%2,%3}, [%4];\n"
                 : "=r"(r[0]), "=r"(r[1]), "=r"(r[2]), "=r"(r[3]) : "r"(addr));
}
__device__ __forceinline__ void sts128(uint32_t addr, uint32_t a, uint32_t b,
                                       uint32_t c, uint32_t d) {
    asm volatile("st.shared.v4.b32 [%0], {%1,%2,%3,%4};\n"
                 :: "r"(addr), "r"(a), "r"(b), "r"(c), "r"(d));
}

__device__ __forceinline__ float2 ldg_cs_f2(const float* p) {
    float2 v;
    asm volatile("ld.global.cs.v2.f32 {%0,%1}, [%2];\n"
                 : "=f"(v.x), "=f"(v.y) : "l"(p));
    return v;
}
__device__ __forceinline__ void stg_cs_f2(float* p, float a, float b) {
    asm volatile("st.global.cs.v2.f32 [%0], {%1,%2};\n"
                 :: "l"(p), "f"(a), "f"(b));
}

// ---------------- SMEM layout (dynamic) ----------------
// [0, 65536)          : W fragments (ks*4096 + ntp*512 + lane*16 + e*8 + j*4)
// [65536, 196608)     : A fragments (ks*8192 + mtile*512 + (lane*16 ^ (ks&1)*64))
// [196608, 197120)    : bias bs[4][32]
static constexpr int SMEM_W  = 0;
static constexpr int SMEM_A  = 65536;
static constexpr int SMEM_BS = 65536 + 131072;
static constexpr int SMEM_TOTAL = SMEM_BS + 512;   // 197120

// ============================================================================
// Fused kernel. grid=148 x 512 threads, 1 CTA/SM.
// blk&3 = qh (hcol quarter); blk>>2 (0..36) strides batch tiles of 256 rows.
// Per tile: convert A (16 coalesced iters) -> sync -> GEMM (R12 shape,
// 16 warps: mgroup=w&7 -> mtiles 2mg,2mg+1; g=w>>3) -> epilogue -> sync.
// ============================================================================
__global__ void __launch_bounds__(512, 1)
lstm_fused_kernel(
    const float* __restrict__ x, const float* __restrict__ h_t,
    const float* __restrict__ c_t,
    const float* __restrict__ Wii, const float* __restrict__ Whi,
    const float* __restrict__ Wif, const float* __restrict__ Whf,
    const float* __restrict__ Wig, const float* __restrict__ Whg,
    const float* __restrict__ Wio, const float* __restrict__ Who,
    const float* __restrict__ b_i, const float* __restrict__ b_f,
    const float* __restrict__ b_g, const float* __restrict__ b_o,
    float* __restrict__ out, int batch, int ntiles)
{
    extern __shared__ char smem[];
    const uint32_t sb = smem_u32(smem);
    const uint32_t sW = sb + SMEM_W;
    const uint32_t sA = sb + SMEM_A;
    float* bs = (float*)(smem + SMEM_BS);

    const int tid  = threadIdx.x;
    const int wid  = tid >> 5;
    const int lane = tid & 31;
    const int blk  = blockIdx.x;
    const int qh   = blk & 3;
    const int cta  = blk >> 2;                 // 0..36
    const int mt_stride = gridDim.x >> 2;      // 37

    // ---- inline W pack: fp32 gmem -> fp16 fragment layout in smem ----
    {
        #pragma unroll
        for (int i = 0; i < 32; i++) {
            const int p  = tid + (i << 9);     // 0..16383 pair index
            const int gl = p >> 7;             // 0..127 : q*32 + hc
            const int kp = p & 127;
            const int q  = gl >> 5;
            const int hc = gl & 31;
            const int k  = kp * 2;

            const int t2   = hc >> 3;
            const int ntp  = q * 2 + (t2 >> 1);
            const int e    = t2 & 1;
            const int l    = (k >> 2) & 3;
            const int j    = (k >> 1) & 1;
            const int ln2  = (hc & 7) * 4 + l;
            const int ks   = k >> 4;

            const float* Wx;
            const float* Wh;
            switch (q) {
                case 0:  Wx = Wii; Wh = Whi; break;
                case 1:  Wx = Wif; Wh = Whf; break;
                case 2:  Wx = Wig; Wh = Whg; break;
                default: Wx = Wio; Wh = Who; break;
            }
            const int hcolg = qh * 32 + hc;
            float2 v;
            if (k < 128) v = ((const float2*)(Wx + hcolg * 128))[kp];
            else         v = ((const float2*)(Wh + hcolg * 128))[kp - 64];

            __half2 hv = __floats2half2_rn(v.x, v.y);
            const uint32_t addr = sW + (uint32_t)(ks * 4096 + ntp * 512
                                                  + ln2 * 16 + e * 8 + j * 4);
            asm volatile("st.shared.b32 [%0], %1;\n"
                         :: "r"(addr), "r"(*(uint32_t*)&hv));
        }
    }
    // ---- biases for this quarter: bs[q][hc] ----
    if (tid < 128) {
        int q  = tid >> 5;
        int hc = tid & 31;
        const float* bp = (q == 0) ? b_i : (q == 1) ? b_f : (q == 2) ? b_g : b_o;
        bs[tid] = bp[qh * 32 + hc];
    }

    // ---- producer geometry (fixed per thread) ----
    // thread = colq(3b) | rowidx(6b): per iteration covers 128 rows x 32 cols
    const int colq   = tid & 7;                // k-quad within 32-col stage
    const int rowidx = tid >> 3;               // 0..63
    const int mtl    = rowidx >> 3;            // mtile within 8-group
    const int rlo8   = rowidx & 7;
    const int ksIn   = colq >> 2;              // ks within stage (= ks&1)
    const int lq     = colq & 3;
    // STS address for (H=0, s=0); per s add 2*8192; H adds 8*512; XOR ksIn*64
    const uint32_t stsBase = sA
        + (uint32_t)(ksIn * 8192 + mtl * 512)
        + (uint32_t)(((rlo8 * 4 + lq) * 16) ^ (ksIn * 64));

    // ---- consumer geometry ----
    const int mgroup = wid & 7;
    const int g      = wid >> 3;
    const uint32_t bLane = sW + (uint32_t)(g * 512 + lane * 16);
    const uint32_t aEven = sA + (uint32_t)(mgroup * 1024 + lane * 16);
    const uint32_t aOdd  = aEven ^ 64u;
    const size_t cbase = (size_t)batch * 128;

    __syncthreads();

    // ---- persistent tile loop ----
    for (int mt = cta; mt < ntiles; mt += mt_stride) {

        // ---- convert A tile: 16 iterations (H: row half, s: 32-col stage) ----
        #pragma unroll 4
        for (int it = 0; it < 16; it++) {
            const int H = it >> 3;             // 0..1
            const int s = it & 7;              // 0..7
            const int row = mt * 256 + (H * 8 + mtl) * 16 + rlo8;
            const int c = s * 32 + colq * 4;
            const float* bsrc = (c < 128) ? x : h_t;
            const int kk = c & 127;

            const float4 v = __ldg((const float4*)(bsrc + (size_t)row * 128 + kk));
            const float4 u = __ldg((const float4*)(bsrc + (size_t)(row + 8) * 128 + kk));

            const uint32_t w0 = cvt_h2(v.x, v.y);
            const uint32_t w1 = cvt_h2(u.x, u.y);
            const uint32_t w2 = cvt_h2(v.z, v.w);
            const uint32_t w3 = cvt_h2(u.z, u.w);

            sts128(stsBase + (uint32_t)(s * 16384 + H * 4096), w0, w1, w2, w3);
        }
        __syncthreads();

        // ---- GEMM ----
        float acc[2][4][2][4];                 // [mtile][gate][e][frag]
        #pragma unroll
        for (int a0 = 0; a0 < 2; a0++)
            #pragma unroll
            for (int a1 = 0; a1 < 4; a1++)
                #pragma unroll
                for (int a2 = 0; a2 < 2; a2++)
                    #pragma unroll
                    for (int a3 = 0; a3 < 4; a3++)
                        acc[a0][a1][a2][a3] = 0.0f;

        #pragma unroll
        for (int ks = 0; ks < 16; ks++) {
            const uint32_t ab = ((ks & 1) ? aOdd : aEven) + (uint32_t)(ks * 8192);
            uint32_t A0[4], A1[4];
            lds128(A0, ab);
            lds128(A1, ab + 512);

            uint32_t B[4][4];
            const uint32_t bb = bLane + (uint32_t)(ks * 4096);
            #pragma unroll
            for (int q = 0; q < 4; q++)
                lds128(B[q], bb + (uint32_t)(q * 1024));

            #pragma unroll
            for (int q = 0; q < 4; q++) {
                mma16816(acc[0][q][0], A0, B[q][0], B[q][1]);
                mma16816(acc[1][q][0], A1, B[q][0], B[q][1]);
                mma16816(acc[0][q][1], A0, B[q][2], B[q][3]);
                mma16816(acc[1][q][1], A1, B[q][2], B[q][3]);
            }
        }

        // ---- epilogue ----
        const int hc0 = (g << 4) + ((lane & 3) << 1);
        const int hcol0 = (qh << 5) + hc0;
        float2 cv[2][2][2];                    // [m][e][rh]
        #pragma unroll
        for (int m = 0; m < 2; m++) {
            const int rr0 = mt * 256 + (mgroup * 2 + m) * 16 + (lane >> 2);
            #pragma unroll
            for (int e = 0; e < 2; e++) {
                const int hcol = hcol0 + e * 8;
                cv[m][e][0] = ldg_cs_f2(c_t + (size_t)rr0 * 128 + hcol);
                cv[m][e][1] = ldg_cs_f2(c_t + (size_t)(rr0 + 8) * 128 + hcol);
            }
        }

        #pragma unroll
        for (int m = 0; m < 2; m++) {
            const int rr0 = mt * 256 + (mgroup * 2 + m) * 16 + (lane >> 2);
            #pragma unroll
            for (int e = 0; e < 2; e++) {
                const int hc32 = hc0 + e * 8;
                const int hcol = hcol0 + e * 8;
                const float bi0 = bs[hc32],      bi1 = bs[hc32 + 1];
                const float bf0 = bs[32 + hc32], bf1 = bs[32 + hc32 + 1];
                const float bg0 = bs[64 + hc32], bg1 = bs[64 + hc32 + 1];
                const float bo0 = bs[96 + hc32], bo1 = bs[96 + hc32 + 1];
                #pragma unroll
                for (int rh = 0; rh < 2; rh++) {
                    const int row = rr0 + rh * 8;
                    const float2 cc = cv[m][e][rh];

                    float ia0 = acc[m][0][e][rh * 2 + 0] + bi0;
                    float ia1 = acc[m][0][e][rh * 2 + 1] + bi1;
                    float fa0 = acc[m][1][e][rh * 2 + 0] + bf0;
                    float fa1 = acc[m][1][e][rh * 2 + 1] + bf1;
                    float ga0 = acc[m][2][e][rh * 2 + 0] + bg0;
                    float ga1 = acc[m][2][e][rh * 2 + 1] + bg1;
                    float oa0 = acc[m][3][e][rh * 2 + 0] + bo0;
                    float oa1 = acc[m][3][e][rh * 2 + 1] + bo1;

                    float it0 = fast_sigmoid(ia0), it1 = fast_sigmoid(ia1);
                    float ft0 = fast_sigmoid(fa0), ft1 = fast_sigmoid(fa1);
                    float gt0 = fast_tanh(ga0),    gt1 = fast_tanh(ga1);
                    float ot0 = fast_sigmoid(oa0), ot1 = fast_sigmoid(oa1);

                    float cn0 = ft0 * cc.x + it0 * gt0;
                    float cn1 = ft1 * cc.y + it1 * gt1;
                    float hn0 = ot0 * fast_tanh(cn0);
                    float hn1 = ot1 * fast_tanh(cn1);

                    stg_cs_f2(out + (size_t)row * 128 + hcol, hn0, hn1);
                    stg_cs_f2(out + cbase + (size_t)row * 128 + hcol, cn0, cn1);
                }
            }
        }
        __syncthreads();   // all consumers done before next tile's STS
    }
}

// ============================================================================
// Host launch — single kernel
// ============================================================================
extern "C" void kernel_launch(void* const* d_in, const int* in_sizes, int n_in,
                              void* d_out, int out_size)
{
    (void)n_in; (void)out_size;
    const float* x   = (const float*)d_in[0];
    const float* h_t = (const float*)d_in[1];
    const float* c_t = (const float*)d_in[2];
    const float* Wii = (const float*)d_in[3];
    const float* Whi = (const float*)d_in[4];
    const float* b_i = (const float*)d_in[5];
    const float* Wif = (const float*)d_in[6];
    const float* Whf = (const float*)d_in[7];
    const float* b_f = (const float*)d_in[8];
    const float* Wig = (const float*)d_in[9];
    const float* Whg = (const float*)d_in[10];
    const float* b_g = (const float*)d_in[11];
    const float* Wio = (const float*)d_in[12];
    const float* Who = (const float*)d_in[13];
    const float* b_o = (const float*)d_in[14];

    const int batch  = in_sizes[0] / 128;
    const int ntiles = batch / 256;            // 256 for batch 65536

    static bool attr_set = false;
    if (!attr_set) {
        cudaFuncSetAttribute(lstm_fused_kernel,
                             cudaFuncAttributeMaxDynamicSharedMemorySize,
                             SMEM_TOTAL);
        attr_set = true;
    }
    lstm_fused_kernel<<<148, 512, SMEM_TOTAL>>>(
        x, h_t, c_t, Wii, Whi, Wif, Whf, Wig, Whg, Wio, Who,
        b_i, b_f, b_g, b_o, (float*)d_out, batch, ntiles);
}

// round 17
// speedup vs baseline: 1.1670x; 1.1670x over previous
#include <cuda_runtime.h>
#include <cuda_fp16.h>
#include <cstdint>

// ============================================================================
// LSTMCell on GB300 via mma.sync (HMMA) — tcgen05 unavailable (compute_103 PTX).
// gates[B,512] = [x|h] @ Wcat^T, fp16 operands / fp32 accum, fused epilogue.
//
// R16 -> R17: warp-specialized single kernel. Warps 0-7 = GEMM consumers
// (R12 shape: 2mt x 8nfrag, acc=64). Warps 8-15 = producers converting the
// NEXT 128-row tile's A (fp32 gmem -> fp16 fragment smem, coalesced LDG.128,
// conflict-free STS.128). Double-buffered 2x64KB A + 64KB W. Handoff via
// named barriers (full/empty per slot); conversion overlaps mma + epilogue.
// ============================================================================

__device__ __forceinline__ uint32_t smem_u32(const void* p) {
    uint32_t a;
    asm("{ .reg .u64 t; cvta.to.shared.u64 t, %1; cvt.u32.u64 %0, t; }"
        : "=r"(a) : "l"(p));
    return a;
}

__device__ __forceinline__ float fast_tanh(float x) {
    float r;
    asm("tanh.approx.f32 %0, %1;" : "=f"(r) : "f"(x));
    return r;
}
__device__ __forceinline__ float fast_sigmoid(float x) {
    return fmaf(0.5f, fast_tanh(0.5f * x), 0.5f);
}

__device__ __forceinline__ uint32_t cvt_h2(float lo, float hi) {
    uint32_t r;
    asm("cvt.rn.f16x2.f32 %0, %1, %2;" : "=r"(r) : "f"(hi), "f"(lo));
    return r;
}

__device__ __forceinline__ void mma16816(float* d, const uint32_t* a,
                                         uint32_t b0, uint32_t b1) {
    asm volatile(
        "mma.sync.aligned.m16n8k16.row.col.f32.f16.f16.f32 "
        "{%0,%1,%2,%3}, {%4,%5,%6,%7}, {%8,%9}, {%0,%1,%2,%3};\n"
        : "+f"(d[0]), "+f"(d[1]), "+f"(d[2]), "+f"(d[3])
        : "r"(a[0]), "r"(a[1]), "r"(a[2]), "r"(a[3]), "r"(b0), "r"(b1));
}

__device__ __forceinline__ void lds128(uint32_t* r, uint32_t addr) {
    asm volatile("ld.shared.v4.b32 {%0,%1,%2,%3}, [%4];\n"
                 : "=r"(r[0]), "=r"(r[1]), "=r"(r[2]), "=r"(r[3]) : "r"(addr));
}
__device__ __forceinline__ void sts128(uint32_t addr, uint32_t a, uint32_t b,
                                       uint32_t c, uint32_t d) {
    asm volatile("st.shared.v4.b32 [%0], {%1,%2,%3,%4};\n"
                 :: "r"(addr), "r"(a), "r"(b), "r"(c), "r"(d));
}

__device__ __forceinline__ float2 ldg_cs_f2(const float* p) {
    float2 v;
    asm volatile("ld.global.cs.v2.f32 {%0,%1}, [%2];\n"
                 : "=f"(v.x), "=f"(v.y) : "l"(p));
    return v;
}
__device__ __forceinline__ void stg_cs_f2(float* p, float a, float b) {
    asm volatile("st.global.cs.v2.f32 [%0], {%1,%2};\n"
                 :: "l"(p), "f"(a), "f"(b));
}

#define BAR_SYNC(id)   asm volatile("bar.sync %0, 512;"   :: "r"(id) : "memory")
#define BAR_ARRIVE(id) asm volatile("bar.arrive %0, 512;" :: "r"(id) : "memory")
#define MEMBAR_CTA()   asm volatile("membar.cta;" ::: "memory")

// ---------------- SMEM layout (dynamic) ----------------
// [0, 65536)       : W fragments (ks*4096 + ntp*512 + lane*16 + e*8 + j*4)
// [65536, 131072)  : A slot 0  (ks*4096 + mtile*512 + (lane*16 ^ (ks&1)*64))
// [131072, 196608) : A slot 1
// [196608, 197120) : bias bs[4][32]
static constexpr int SMEM_W  = 0;
static constexpr int SMEM_A0 = 65536;
static constexpr int SMEM_BS = 196608;
static constexpr int SMEM_TOTAL = SMEM_BS + 512;   // 197120

// ============================================================================
// Fused warp-specialized kernel. grid=148 x 512 threads, 1 CTA/SM.
// blk&3 = qh (hcol quarter); blk>>2 (0..36) strides batch tiles of 128 rows.
// Consumers (wid 0-7): mgroup=wid&3 -> mtiles 2mg,2mg+1; g=wid>>2.
// Producers (wid 8-15): convert tile A into slot i&1, 2 tiles ahead max.
// ============================================================================
__global__ void __launch_bounds__(512, 1)
lstm_fused_kernel(
    const float* __restrict__ x, const float* __restrict__ h_t,
    const float* __restrict__ c_t,
    const float* __restrict__ Wii, const float* __restrict__ Whi,
    const float* __restrict__ Wif, const float* __restrict__ Whf,
    const float* __restrict__ Wig, const float* __restrict__ Whg,
    const float* __restrict__ Wio, const float* __restrict__ Who,
    const float* __restrict__ b_i, const float* __restrict__ b_f,
    const float* __restrict__ b_g, const float* __restrict__ b_o,
    float* __restrict__ out, int batch, int ntiles)
{
    extern __shared__ char smem[];
    const uint32_t sb = smem_u32(smem);
    const uint32_t sW = sb + SMEM_W;
    const uint32_t sA = sb + SMEM_A0;
    float* bs = (float*)(smem + SMEM_BS);

    const int tid  = threadIdx.x;
    const int wid  = tid >> 5;
    const int lane = tid & 31;
    const int blk  = blockIdx.x;
    const int qh   = blk & 3;
    const int cta  = blk >> 2;                 // 0..36
    const int mt_stride = gridDim.x >> 2;      // 37

    // ---- inline W pack: fp32 gmem -> fp16 fragment layout in smem ----
    {
        #pragma unroll
        for (int i = 0; i < 32; i++) {
            const int p  = tid + (i << 9);     // 0..16383 pair index
            const int gl = p >> 7;             // q*32 + hc
            const int kp = p & 127;
            const int q  = gl >> 5;
            const int hc = gl & 31;
            const int k  = kp * 2;

            const int t2   = hc >> 3;
            const int ntp  = q * 2 + (t2 >> 1);
            const int e    = t2 & 1;
            const int l    = (k >> 2) & 3;
            const int j    = (k >> 1) & 1;
            const int ln2  = (hc & 7) * 4 + l;
            const int ks   = k >> 4;

            const float* Wx;
            const float* Wh;
            switch (q) {
                case 0:  Wx = Wii; Wh = Whi; break;
                case 1:  Wx = Wif; Wh = Whf; break;
                case 2:  Wx = Wig; Wh = Whg; break;
                default: Wx = Wio; Wh = Who; break;
            }
            const int hcolg = qh * 32 + hc;
            float2 v;
            if (k < 128) v = ((const float2*)(Wx + hcolg * 128))[kp];
            else         v = ((const float2*)(Wh + hcolg * 128))[kp - 64];

            __half2 hv = __floats2half2_rn(v.x, v.y);
            const uint32_t addr = sW + (uint32_t)(ks * 4096 + ntp * 512
                                                  + ln2 * 16 + e * 8 + j * 4);
            asm volatile("st.shared.b32 [%0], %1;\n"
                         :: "r"(addr), "r"(*(uint32_t*)&hv));
        }
    }
    if (tid < 128) {
        int q  = tid >> 5;
        int hc = tid & 31;
        const float* bp = (q == 0) ? b_i : (q == 1) ? b_f : (q == 2) ? b_g : b_o;
        bs[tid] = bp[qh * 32 + hc];
    }
    __syncthreads();

    const size_t cbase = (size_t)batch * 128;

    if (wid >= 8) {
        // ===================== PRODUCER =====================
        const int tid2  = tid - 256;
        const int colq  = tid2 & 7;            // k-quad within 32-col stage
        const int rowi  = tid2 >> 3;           // 0..31
        const int mtl   = rowi >> 3;           // 0..3
        const int rlo8  = rowi & 7;
        const int ksIn  = colq >> 2;
        const int lq    = colq & 3;
        const uint32_t stsTh = (uint32_t)(ksIn * 4096 + mtl * 512)
                             + (uint32_t)(((rlo8 * 4 + lq) * 16) ^ (ksIn * 64));

        int i = 0;
        for (int mt = cta; mt < ntiles; mt += mt_stride, i++) {
            const int slot = i & 1;
            if (i >= 2) BAR_SYNC(3 + slot);    // wait empty[slot]
            const uint32_t dst = sA + (uint32_t)(slot << 16) + stsTh;

            #pragma unroll 4
            for (int it = 0; it < 16; it++) {
                const int H = it >> 3;         // mtile group
                const int s = it & 7;          // 32-col stage
                const int row = mt * 128 + (H * 4 + mtl) * 16 + rlo8;
                const int c = s * 32 + colq * 4;
                const float* bsrc = (c < 128) ? x : h_t;
                const int kk = c & 127;

                const float4 v = __ldg((const float4*)(bsrc + (size_t)row * 128 + kk));
                const float4 u = __ldg((const float4*)(bsrc + (size_t)(row + 8) * 128 + kk));

                sts128(dst + (uint32_t)(s * 8192 + H * 2048),
                       cvt_h2(v.x, v.y), cvt_h2(u.x, u.y),
                       cvt_h2(v.z, v.w), cvt_h2(u.z, u.w));
            }
            MEMBAR_CTA();
            BAR_ARRIVE(1 + slot);              // signal full[slot]
        }
    } else {
        // ===================== CONSUMER =====================
        const int mgroup = wid & 3;
        const int g      = wid >> 2;
        const uint32_t bLane = sW + (uint32_t)(g * 512 + lane * 16);
        const uint32_t aEven = (uint32_t)(mgroup * 1024 + lane * 16);
        const uint32_t aOdd  = aEven ^ 64u;

        int i = 0;
        for (int mt = cta; mt < ntiles; mt += mt_stride, i++) {
            const int slot = i & 1;
            BAR_SYNC(1 + slot);                // wait full[slot]
            const uint32_t sAs = sA + (uint32_t)(slot << 16);

            float acc[2][4][2][4];             // [mtile][gate][e][frag]
            #pragma unroll
            for (int a0 = 0; a0 < 2; a0++)
                #pragma unroll
                for (int a1 = 0; a1 < 4; a1++)
                    #pragma unroll
                    for (int a2 = 0; a2 < 2; a2++)
                        #pragma unroll
                        for (int a3 = 0; a3 < 4; a3++)
                            acc[a0][a1][a2][a3] = 0.0f;

            #pragma unroll
            for (int ks = 0; ks < 16; ks++) {
                const uint32_t ab = sAs + ((ks & 1) ? aOdd : aEven)
                                  + (uint32_t)(ks * 4096);
                uint32_t A0[4], A1[4];
                lds128(A0, ab);
                lds128(A1, ab + 512);

                uint32_t B[4][4];
                const uint32_t bb = bLane + (uint32_t)(ks * 4096);
                #pragma unroll
                for (int q = 0; q < 4; q++)
                    lds128(B[q], bb + (uint32_t)(q * 1024));

                #pragma unroll
                for (int q = 0; q < 4; q++) {
                    mma16816(acc[0][q][0], A0, B[q][0], B[q][1]);
                    mma16816(acc[1][q][0], A1, B[q][0], B[q][1]);
                    mma16816(acc[0][q][1], A0, B[q][2], B[q][3]);
                    mma16816(acc[1][q][1], A1, B[q][2], B[q][3]);
                }
            }
            MEMBAR_CTA();
            BAR_ARRIVE(3 + slot);              // signal empty[slot] pre-epilogue

            // ---- epilogue ----
            const int hc0 = (g << 4) + ((lane & 3) << 1);
            const int hcol0 = (qh << 5) + hc0;
            float2 cv[2][2][2];                // [m][e][rh]
            #pragma unroll
            for (int m = 0; m < 2; m++) {
                const int rr0 = mt * 128 + (mgroup * 2 + m) * 16 + (lane >> 2);
                #pragma unroll
                for (int e = 0; e < 2; e++) {
                    const int hcol = hcol0 + e * 8;
                    cv[m][e][0] = ldg_cs_f2(c_t + (size_t)rr0 * 128 + hcol);
                    cv[m][e][1] = ldg_cs_f2(c_t + (size_t)(rr0 + 8) * 128 + hcol);
                }
            }

            #pragma unroll
            for (int m = 0; m < 2; m++) {
                const int rr0 = mt * 128 + (mgroup * 2 + m) * 16 + (lane >> 2);
                #pragma unroll
                for (int e = 0; e < 2; e++) {
                    const int hc32 = hc0 + e * 8;
                    const int hcol = hcol0 + e * 8;
                    const float bi0 = bs[hc32],      bi1 = bs[hc32 + 1];
                    const float bf0 = bs[32 + hc32], bf1 = bs[32 + hc32 + 1];
                    const float bg0 = bs[64 + hc32], bg1 = bs[64 + hc32 + 1];
                    const float bo0 = bs[96 + hc32], bo1 = bs[96 + hc32 + 1];
                    #pragma unroll
                    for (int rh = 0; rh < 2; rh++) {
                        const int row = rr0 + rh * 8;
                        const float2 cc = cv[m][e][rh];

                        float ia0 = acc[m][0][e][rh * 2 + 0] + bi0;
                        float ia1 = acc[m][0][e][rh * 2 + 1] + bi1;
                        float fa0 = acc[m][1][e][rh * 2 + 0] + bf0;
                        float fa1 = acc[m][1][e][rh * 2 + 1] + bf1;
                        float ga0 = acc[m][2][e][rh * 2 + 0] + bg0;
                        float ga1 = acc[m][2][e][rh * 2 + 1] + bg1;
                        float oa0 = acc[m][3][e][rh * 2 + 0] + bo0;
                        float oa1 = acc[m][3][e][rh * 2 + 1] + bo1;

                        float it0 = fast_sigmoid(ia0), it1 = fast_sigmoid(ia1);
                        float ft0 = fast_sigmoid(fa0), ft1 = fast_sigmoid(fa1);
                        float gt0 = fast_tanh(ga0),    gt1 = fast_tanh(ga1);
                        float ot0 = fast_sigmoid(oa0), ot1 = fast_sigmoid(oa1);

                        float cn0 = ft0 * cc.x + it0 * gt0;
                        float cn1 = ft1 * cc.y + it1 * gt1;
                        float hn0 = ot0 * fast_tanh(cn0);
                        float hn1 = ot1 * fast_tanh(cn1);

                        stg_cs_f2(out + (size_t)row * 128 + hcol, hn0, hn1);
                        stg_cs_f2(out + cbase + (size_t)row * 128 + hcol, cn0, cn1);
                    }
                }
            }
        }
    }
}

// ============================================================================
// Host launch — single kernel
// ============================================================================
extern "C" void kernel_launch(void* const* d_in, const int* in_sizes, int n_in,
                              void* d_out, int out_size)
{
    (void)n_in; (void)out_size;
    const float* x   = (const float*)d_in[0];
    const float* h_t = (const float*)d_in[1];
    const float* c_t = (const float*)d_in[2];
    const float* Wii = (const float*)d_in[3];
    const float* Whi = (const float*)d_in[4];
    const float* b_i = (const float*)d_in[5];
    const float* Wif = (const float*)d_in[6];
    const float* Whf = (const float*)d_in[7];
    const float* b_f = (const float*)d_in[8];
    const float* Wig = (const float*)d_in[9];
    const float* Whg = (const float*)d_in[10];
    const float* b_g = (const float*)d_in[11];
    const float* Wio = (const float*)d_in[12];
    const float* Who = (const float*)d_in[13];
    const float* b_o = (const float*)d_in[14];

    const int batch  = in_sizes[0] / 128;
    const int ntiles = batch / 128;            // 512 for batch 65536

    static bool attr_set = false;
    if (!attr_set) {
        cudaFuncSetAttribute(lstm_fused_kernel,
                             cudaFuncAttributeMaxDynamicSharedMemorySize,
                             SMEM_TOTAL);
        attr_set = true;
    }
    lstm_fused_kernel<<<148, 512, SMEM_TOTAL>>>(
        x, h_t, c_t, Wii, Whi, Wif, Whf, Wig, Whg, Wio, Who,
        b_i, b_f, b_g, b_o, (float*)d_out, batch, ntiles);
}